// round 3
// baseline (speedup 1.0000x reference)
#include <cuda_runtime.h>
#include <cstdint>

#define ALPHA_ 0.2f
#define B_    16
#define N_    1024
#define IND_  128
#define HEADS_ 2
#define HD_   64
#define BH_   (B_*HEADS_)

// Scratch (no cudaMalloc allowed): hp[bh][n][d], e_src[bh][n], e_dst[bh][n]
__device__ float g_hp[BH_ * N_ * HD_];
__device__ float g_esrc[BH_ * N_];
__device__ float g_edst[BH_ * N_];

__device__ __forceinline__ unsigned long long ffma2(unsigned long long a,
                                                    unsigned long long b,
                                                    unsigned long long c) {
    unsigned long long d;
    asm("fma.rn.f32x2 %0, %1, %2, %3;" : "=l"(d) : "l"(a), "l"(b), "l"(c));
    return d;
}
__device__ __forceinline__ unsigned long long pack2(float x, float y) {
    unsigned long long d;
    asm("mov.b64 %0, {%1, %2};" : "=l"(d) : "f"(x), "f"(y));
    return d;
}
__device__ __forceinline__ float2 unpack2(unsigned long long v) {
    float2 r;
    asm("mov.b64 {%0, %1}, %2;" : "=f"(r.x), "=f"(r.y) : "l"(v));
    return r;
}

// ============================================================================
// Kernel A: hp[b,h,n,d] = h[b,n,:] @ W[h,:,d]   (16384x128 @ 128x128)
// grid 256 CTAs (64 rows each), 256 threads, thread tile 4n x 8d, f32x2 FMA.
// ============================================================================
#define A_HS 129   // padded stride so hs[n][k] is bank-conflict-free
__global__ void __launch_bounds__(256) proj_kernel(const float* __restrict__ h,
                                                   const float* __restrict__ W) {
    extern __shared__ float sm[];
    float* hs = sm;                   // 64 x 129
    float* Ws = sm + 64 * A_HS;       // [k][hd], 128 x 128

    int t = threadIdx.x;
    int r0 = blockIdx.x * 64;         // global row = b*1024 + n (64 | 1024)

    // load h tile: 64x128 floats (8 float4 per thread)
    #pragma unroll
    for (int i = 0; i < 8; i++) {
        int f = t + i * 256;          // 0..2047 float4s
        int row = f >> 5;             // 32 float4 per row
        int c4  = f & 31;
        float4 v = *(const float4*)(h + (size_t)(r0 + row) * IND_ + c4 * 4);
        float* dst = hs + row * A_HS + c4 * 4;
        dst[0] = v.x; dst[1] = v.y; dst[2] = v.z; dst[3] = v.w;
    }
    // load W into [k][hd] layout: 16384 floats (16 float4 per thread)
    #pragma unroll
    for (int i = 0; i < 16; i++) {
        int f = t + i * 256;          // float4 index
        int lin = f * 4;
        int k  = lin >> 7;
        int hd = lin & 127;
        int hh = hd >> 6;
        int d  = hd & 63;
        float4 v = *(const float4*)(W + (size_t)hh * (IND_ * HD_) + k * HD_ + d);
        *(float4*)(Ws + k * 128 + hd) = v;
    }
    __syncthreads();

    // thread map: warp covers 16n x 32d (4 ng-groups x 8 dg-groups)
    int w = t >> 5, lane = t & 31;
    int ng = (w & 3) * 4 + (lane >> 3);   // 0..15
    int dg = (w >> 2) * 8 + (lane & 7);   // 0..15
    int nq = ng * 4, dq = dg * 8;

    unsigned long long acc[4][4];
    #pragma unroll
    for (int i = 0; i < 4; i++)
        #pragma unroll
        for (int j = 0; j < 4; j++) acc[i][j] = 0ull;

    #pragma unroll 8
    for (int k = 0; k < 128; k++) {
        ulonglong2 w0 = *(const ulonglong2*)(Ws + k * 128 + dq);
        ulonglong2 w1 = *(const ulonglong2*)(Ws + k * 128 + dq + 4);
        #pragma unroll
        for (int i = 0; i < 4; i++) {
            float hv = hs[(nq + i) * A_HS + k];
            unsigned long long hd2 = pack2(hv, hv);
            acc[i][0] = ffma2(hd2, w0.x, acc[i][0]);
            acc[i][1] = ffma2(hd2, w0.y, acc[i][1]);
            acc[i][2] = ffma2(hd2, w1.x, acc[i][2]);
            acc[i][3] = ffma2(hd2, w1.y, acc[i][3]);
        }
    }

    int b    = r0 >> 10;
    int head = dq >> 6;
    int d0   = dq & 63;
    #pragma unroll
    for (int i = 0; i < 4; i++) {
        int n = (r0 & 1023) + nq + i;
        float* dst = g_hp + ((size_t)(b * HEADS_ + head) * N_ + n) * HD_ + d0;
        float2 p0 = unpack2(acc[i][0]), p1 = unpack2(acc[i][1]);
        float2 p2 = unpack2(acc[i][2]), p3 = unpack2(acc[i][3]);
        *(float4*)(dst)     = make_float4(p0.x, p0.y, p1.x, p1.y);
        *(float4*)(dst + 4) = make_float4(p2.x, p2.y, p3.x, p3.y);
    }
}

// ============================================================================
// Kernel B: e_src[bh,n] = hp[bh,n,:]·a_src[h], e_dst likewise. One warp per row.
// ============================================================================
__global__ void __launch_bounds__(256) escore_kernel(const float* __restrict__ a) {
    int gw   = blockIdx.x * 8 + (threadIdx.x >> 5);   // 0..32767
    int lane = threadIdx.x & 31;
    int bh   = gw >> 10;
    int n    = gw & 1023;
    int head = bh & 1;

    float2 v  = *(const float2*)(g_hp + ((size_t)bh * N_ + n) * HD_ + lane * 2);
    float2 as = *(const float2*)(a + head * IND_ + lane * 2);
    float2 ad = *(const float2*)(a + head * IND_ + HD_ + lane * 2);
    float ps = v.x * as.x + v.y * as.y;
    float pd = v.x * ad.x + v.y * ad.y;
    #pragma unroll
    for (int o = 16; o; o >>= 1) {
        ps += __shfl_xor_sync(0xFFFFFFFFu, ps, o);
        pd += __shfl_xor_sync(0xFFFFFFFFu, pd, o);
    }
    if (lane == 0) { g_esrc[gw] = ps; g_edst[gw] = pd; }
}

// ============================================================================
// Kernel C: fused scores + softmax + att@V + residual + ELU.
// grid (16 n-tiles, 32 bh), 256 threads, 64n x 64d output tile,
// 16 m-tiles of 64. w stored pre-duplicated {w,w} -> zero-mov f32x2 GEMM.
// ============================================================================
#define C_EDST 0
#define C_VT   1024
#define C_WT2  (1024 + 4096)                  // float2[64*64] = 8192 floats
#define C_ESRC (1024 + 4096 + 8192)
#define C_DSUM (C_ESRC + 64)
#define C_RED  (C_DSUM + 256)
#define C_FLOATS (C_RED + 8)

__global__ void __launch_bounds__(256) attn_kernel(const float* __restrict__ h_in,
                                                   float* __restrict__ out) {
    extern __shared__ float sm[];
    float*  edst_s = sm + C_EDST;
    float*  Vt     = sm + C_VT;
    float2* Wt2    = (float2*)(sm + C_WT2);
    float*  esrc_s = sm + C_ESRC;   // later reused as inv_denom
    float*  dsum   = sm + C_DSUM;
    float*  red    = sm + C_RED;

    int t    = threadIdx.x;
    int bh   = blockIdx.y;
    int b    = bh >> 1;
    int head = bh & 1;
    int n0   = blockIdx.x * 64;
    const float* hpb = g_hp + (size_t)bh * (N_ * HD_);

    // ---- prologue: e_dst -> smem, block max; e_src tile -> smem ----
    float4 ed = *(const float4*)(g_edst + bh * N_ + t * 4);
    *(float4*)(edst_s + t * 4) = ed;
    float lm = fmaxf(fmaxf(ed.x, ed.y), fmaxf(ed.z, ed.w));
    #pragma unroll
    for (int o = 16; o; o >>= 1) lm = fmaxf(lm, __shfl_xor_sync(0xFFFFFFFFu, lm, o));
    if ((t & 31) == 0) red[t >> 5] = lm;
    if (t < 64) esrc_s[t] = g_esrc[bh * N_ + n0 + t];

    // prefetch V tile 0 into registers
    float4 vpre[4];
    #pragma unroll
    for (int i = 0; i < 4; i++) {
        int f = t + i * 256; int row = f >> 4; int c4 = f & 15;
        vpre[i] = *(const float4*)(hpb + row * HD_ + c4 * 4);
    }
    __syncthreads();
    if (t == 0) {
        float m = red[0];
        #pragma unroll
        for (int i = 1; i < 8; i++) m = fmaxf(m, red[i]);
        red[0] = m;
    }
    __syncthreads();
    float Mx = red[0];

    // score-phase map: thread -> (n = t&63, m-chunk = t>>6)
    int sn = t & 63, mi = t >> 6;
    float es_n = esrc_s[sn];
    float rt_  = es_n + Mx;
    float rm_n = fmaxf(rt_, ALPHA_ * rt_);    // known row max (LRelu monotone)
    float dpart = 0.f;

    // GEMM map: warp = 16n x 32d (4 ng x 8 dg)
    int w = t >> 5, lane = t & 31;
    int ng = (w & 3) * 4 + (lane >> 3);
    int dg = (w >> 2) * 8 + (lane & 7);
    int nq = ng * 4, dq = dg * 4;

    unsigned long long acc[4][2];
    #pragma unroll
    for (int i = 0; i < 4; i++) { acc[i][0] = 0ull; acc[i][1] = 0ull; }

    for (int mt = 0; mt < 16; mt++) {
        // commit prefetched V tile
        #pragma unroll
        for (int i = 0; i < 4; i++) {
            int f = t + i * 256;
            *(float4*)(Vt + f * 4) = vpre[i];
        }
        // scores: w = exp(LRelu(esrc+edst) - rowmax), stored duplicated {w,w}
        #pragma unroll
        for (int j = 0; j < 16; j++) {
            int ml = mi * 16 + j;
            float s = es_n + edst_s[mt * 64 + ml];
            s = fmaxf(s, ALPHA_ * s);
            float wgt = __expf(s - rm_n);
            dpart += wgt;
            Wt2[ml * 64 + sn] = make_float2(wgt, wgt);
        }
        __syncthreads();
        // prefetch next V tile (overlaps GEMM)
        if (mt < 15) {
            #pragma unroll
            for (int i = 0; i < 4; i++) {
                int f = t + i * 256; int row = f >> 4; int c4 = f & 15;
                vpre[i] = *(const float4*)(hpb + ((mt + 1) * 64 + row) * HD_ + c4 * 4);
            }
        }
        // f32x2 GEMM: per m -> 3x LDS.128 + 8x ffma2, zero packing movs
        #pragma unroll 4
        for (int mm = 0; mm < 64; mm++) {
            ulonglong2 wa = *(const ulonglong2*)(Wt2 + mm * 64 + nq);
            ulonglong2 wb = *(const ulonglong2*)(Wt2 + mm * 64 + nq + 2);
            ulonglong2 vv = *(const ulonglong2*)(Vt + mm * 64 + dq);
            acc[0][0] = ffma2(wa.x, vv.x, acc[0][0]);
            acc[0][1] = ffma2(wa.x, vv.y, acc[0][1]);
            acc[1][0] = ffma2(wa.y, vv.x, acc[1][0]);
            acc[1][1] = ffma2(wa.y, vv.y, acc[1][1]);
            acc[2][0] = ffma2(wb.x, vv.x, acc[2][0]);
            acc[2][1] = ffma2(wb.x, vv.y, acc[2][1]);
            acc[3][0] = ffma2(wb.y, vv.x, acc[3][0]);
            acc[3][1] = ffma2(wb.y, vv.y, acc[3][1]);
        }
        __syncthreads();
    }

    // denominator reduction (4 partials per n)
    dsum[mi * 64 + sn] = dpart;
    __syncthreads();
    if (t < 64) {
        float s = dsum[t] + dsum[64 + t] + dsum[128 + t] + dsum[192 + t];
        esrc_s[t] = 1.0f / s;      // reuse as inv_denom
    }
    __syncthreads();

    // epilogue: normalize, residual (in_dim==out_dim), ELU, store
    #pragma unroll
    for (int i = 0; i < 4; i++) {
        int n = n0 + nq + i;
        float inv = esrc_s[nq + i];
        float2 p0 = unpack2(acc[i][0]);
        float2 p1 = unpack2(acc[i][1]);
        size_t base = ((size_t)b * N_ + n) * IND_ + head * HD_ + dq;
        float4 hv = *(const float4*)(h_in + base);
        float4 o;
        o.x = p0.x * inv + hv.x;
        o.y = p0.y * inv + hv.y;
        o.z = p1.x * inv + hv.z;
        o.w = p1.y * inv + hv.w;
        o.x = o.x > 0.f ? o.x : expm1f(o.x);
        o.y = o.y > 0.f ? o.y : expm1f(o.y);
        o.z = o.z > 0.f ? o.z : expm1f(o.z);
        o.w = o.w > 0.f ? o.w : expm1f(o.w);
        *(float4*)(out + base) = o;
    }
}

// ============================================================================
extern "C" void kernel_launch(void* const* d_in, const int* in_sizes, int n_in,
                              void* d_out, int out_size) {
    const float* h = (const float*)d_in[0];
    const float* W = (const float*)d_in[1];
    const float* a = (const float*)d_in[2];
    float* out = (float*)d_out;

    const int smemA = (64 * A_HS + 128 * 128) * 4;   // 98560 B
    const int smemC = C_FLOATS * 4;                  // ~54.6 KB
    cudaFuncSetAttribute(proj_kernel, cudaFuncAttributeMaxDynamicSharedMemorySize, smemA);
    cudaFuncSetAttribute(attn_kernel, cudaFuncAttributeMaxDynamicSharedMemorySize, smemC);

    proj_kernel<<<256, 256, smemA>>>(h, W);
    escore_kernel<<<4096, 256>>>(a);
    attn_kernel<<<dim3(16, 32), 256, smemC>>>(h, out);
    (void)in_sizes; (void)n_in; (void)out_size;
}

// round 6
// speedup vs baseline: 3.2544x; 3.2544x over previous
#include <cuda_runtime.h>
#include <cstdint>

#define ALPHA_ 0.2f
#define LOG2E_ 1.4426950408889634f
#define B_    16
#define N_    1024
#define IND_  128
#define HEADS_ 2
#define HD_   64
#define BH_   (B_*HEADS_)

// Scratch: hpT[bh][d][m] (m-contiguous), e_src, e_dst
__device__ float g_hpT[BH_ * HD_ * N_];
__device__ float g_esrc[BH_ * N_];
__device__ float g_edst[BH_ * N_];

// ---------------------------------------------------------------- helpers
__device__ __forceinline__ unsigned long long ffma2(unsigned long long a,
                                                    unsigned long long b,
                                                    unsigned long long c) {
    unsigned long long d;
    asm("fma.rn.f32x2 %0, %1, %2, %3;" : "=l"(d) : "l"(a), "l"(b), "l"(c));
    return d;
}
__device__ __forceinline__ unsigned long long pack2(float x, float y) {
    unsigned long long d;
    asm("mov.b64 %0, {%1, %2};" : "=l"(d) : "f"(x), "f"(y));
    return d;
}
__device__ __forceinline__ float2 unpack2(unsigned long long v) {
    float2 r;
    asm("mov.b64 {%0, %1}, %2;" : "=f"(r.x), "=f"(r.y) : "l"(v));
    return r;
}
__device__ __forceinline__ float ex2f(float x) {
    float y;
    asm("ex2.approx.ftz.f32 %0, %1;" : "=f"(y) : "f"(x));
    return y;
}
__device__ __forceinline__ uint32_t tf32c(float x) {
    uint32_t r;
    asm("cvt.rna.tf32.f32 %0, %1;" : "=r"(r) : "f"(x));
    return r;
}
__device__ __forceinline__ void mma_tf32(float& c0, float& c1, float& c2, float& c3,
                                         uint32_t a0, uint32_t a1, uint32_t a2, uint32_t a3,
                                         uint32_t b0, uint32_t b1) {
    asm volatile(
        "mma.sync.aligned.m16n8k8.row.col.f32.tf32.tf32.f32 "
        "{%0,%1,%2,%3}, {%4,%5,%6,%7}, {%8,%9}, {%0,%1,%2,%3};"
        : "+f"(c0), "+f"(c1), "+f"(c2), "+f"(c3)
        : "r"(a0), "r"(a1), "r"(a2), "r"(a3), "r"(b0), "r"(b1));
}

// ============================================================================
// Kernel A: hp = h @ W (exact fp32 f32x2), head-split for occupancy.
// CTA = 64 rows x 1 head (64 d). Epilogue: hpT[d][m] + e_src/e_dst.
// grid (256, 2), 256 threads, smem 65.8KB -> 3 CTAs/SM.
// ============================================================================
#define A_HS 129
__global__ void __launch_bounds__(256) proj_kernel(const float* __restrict__ h,
                                                   const float* __restrict__ W,
                                                   const float* __restrict__ a) {
    extern __shared__ float sm[];
    float* hs = sm;                   // 64 x 129
    float* Ws = sm + 64 * A_HS;       // [k][d], 128 x 64

    int t = threadIdx.x;
    int r0 = blockIdx.x * 64;
    int head = blockIdx.y;

    // h tile: 64x128 floats (8 float4/thread)
    #pragma unroll
    for (int i = 0; i < 8; i++) {
        int f = t + i * 256;
        int row = f >> 5, c4 = f & 31;
        float4 v = *(const float4*)(h + (size_t)(r0 + row) * IND_ + c4 * 4);
        float* dst = hs + row * A_HS + c4 * 4;
        dst[0] = v.x; dst[1] = v.y; dst[2] = v.z; dst[3] = v.w;
    }
    // W[head]: 128x64 floats (8 float4/thread)
    #pragma unroll
    for (int i = 0; i < 8; i++) {
        int f = t + i * 256;
        int lin = f * 4;
        int k = lin >> 6, d = lin & 63;
        float4 v = *(const float4*)(W + (size_t)head * (IND_ * HD_) + k * HD_ + d);
        *(float4*)(Ws + k * 64 + d) = v;
    }
    __syncthreads();

    int w = t >> 5, lane = t & 31;
    int ng = (w & 3) * 4 + (lane >> 3);   // 0..15
    int dg = (w >> 2) * 8 + (lane & 7);   // 0..15
    int nq = ng * 4, dq = dg * 4;

    unsigned long long acc[4][2];
    #pragma unroll
    for (int i = 0; i < 4; i++) { acc[i][0] = 0ull; acc[i][1] = 0ull; }

    #pragma unroll 8
    for (int k = 0; k < 128; k++) {
        ulonglong2 wv = *(const ulonglong2*)(Ws + k * 64 + dq);
        #pragma unroll
        for (int i = 0; i < 4; i++) {
            float hv = hs[(nq + i) * A_HS + k];
            unsigned long long h2 = pack2(hv, hv);
            acc[i][0] = ffma2(h2, wv.x, acc[i][0]);
            acc[i][1] = ffma2(h2, wv.y, acc[i][1]);
        }
    }
    __syncthreads();   // smem front reused as psum scratch

    float hpf[4][4];
    #pragma unroll
    for (int i = 0; i < 4; i++) {
        float2 p0 = unpack2(acc[i][0]), p1 = unpack2(acc[i][1]);
        hpf[i][0] = p0.x; hpf[i][1] = p0.y; hpf[i][2] = p1.x; hpf[i][3] = p1.y;
    }

    int b = r0 >> 10, nr0 = r0 & 1023;
    // hpT[bh][d][m] stores (float4 along m)
    #pragma unroll
    for (int j = 0; j < 4; j++) {
        float4 v = make_float4(hpf[0][j], hpf[1][j], hpf[2][j], hpf[3][j]);
        *(float4*)(g_hpT + (((size_t)(b * HEADS_ + head) * HD_ + dq + j) << 10) + nr0 + nq) = v;
    }

    // e_src / e_dst partials
    const float* ah = a + head * (2 * HD_);
    float4 As = *(const float4*)(ah + dq);
    float4 Ad = *(const float4*)(ah + HD_ + dq);
    float* psrc = sm;
    float* pdst = sm + 1024;
    #pragma unroll
    for (int i = 0; i < 4; i++) {
        float ps = hpf[i][0] * As.x + hpf[i][1] * As.y + hpf[i][2] * As.z + hpf[i][3] * As.w;
        float pd = hpf[i][0] * Ad.x + hpf[i][1] * Ad.y + hpf[i][2] * Ad.z + hpf[i][3] * Ad.w;
        psrc[(nq + i) * 16 + dg] = ps;
        pdst[(nq + i) * 16 + dg] = pd;
    }
    __syncthreads();

    if (t < 128) {
        int sel = t >> 6, n = t & 63;
        const float* bp = (sel ? pdst : psrc) + n * 16;
        float s = 0.f;
        #pragma unroll
        for (int q = 0; q < 16; q++) s += bp[q];
        float* dst = sel ? g_edst : g_esrc;
        dst[(size_t)(b * HEADS_ + head) * N_ + nr0 + n] = s;
    }
}

// ============================================================================
// Kernel C: mma.sync tf32 attention. CTA = 128 n x 64 d, one bh; warp = 16 n.
// A-fragment (exp weights) computed in registers in fragment layout; V tiles
// (64 m) double-buffered in smem [d][stride 68] as tf32 bits.
// grid (8, 32), 256 threads, smem 38.6KB.
// ============================================================================
#define VT_STRIDE 68
#define SO_EDST 0
#define SO_ESRC 4096
#define SO_RED  4608
#define SO_VT0  4736
#define SO_VT1  (SO_VT0 + 64 * VT_STRIDE * 4)
#define SMEM_C  (SO_VT1 + 64 * VT_STRIDE * 4)

__global__ void __launch_bounds__(256) attn_kernel(const float* __restrict__ h_in,
                                                   float* __restrict__ out) {
    extern __shared__ char smc[];
    float* edst_s = (float*)(smc + SO_EDST);
    float* esrc_s = (float*)(smc + SO_ESRC);
    float* red    = (float*)(smc + SO_RED);
    uint32_t* vt0 = (uint32_t*)(smc + SO_VT0);
    uint32_t* vt1 = (uint32_t*)(smc + SO_VT1);

    int t = threadIdx.x, w = t >> 5, lane = t & 31;
    int bh = blockIdx.y, b = bh >> 1, head = bh & 1;
    int n0 = blockIdx.x * 128;
    const float* hpT_b = g_hpT + (size_t)bh * (HD_ * N_);

    // e_dst -> smem + global max; e_src rows -> smem
    float4 ed = *(const float4*)(g_edst + bh * N_ + t * 4);
    *(float4*)(edst_s + t * 4) = ed;
    float lm = fmaxf(fmaxf(ed.x, ed.y), fmaxf(ed.z, ed.w));
    #pragma unroll
    for (int o = 16; o; o >>= 1) lm = fmaxf(lm, __shfl_xor_sync(0xFFFFFFFFu, lm, o));
    if (lane == 0) red[w] = lm;
    if (t < 128) esrc_s[t] = g_esrc[bh * N_ + n0 + t];
    __syncthreads();
    if (t == 0) {
        float m = red[0];
        #pragma unroll
        for (int i = 1; i < 8; i++) m = fmaxf(m, red[i]);
        red[0] = m;
    }
    __syncthreads();
    float Mx = red[0];

    int qr = lane >> 2, qm = lane & 3;
    int r = w * 16 + qr;                    // rows r and r+8
    float es0 = esrc_s[r], es1 = esrc_s[r + 8];
    float s0 = es0 + Mx, s1 = es1 + Mx;
    float rm0 = fmaxf(s0, ALPHA_ * s0), rm1 = fmaxf(s1, ALPHA_ * s1);
    float cb0 = -rm0 * LOG2E_, cb1 = -rm1 * LOG2E_;

    // stage V tile 0 (cvt to tf32 bits, [d][VT_STRIDE])
    float4 pf[4];
    #pragma unroll
    for (int i = 0; i < 4; i++) {
        int f = t + i * 256, d = f >> 4, m4 = f & 15;
        pf[i] = *(const float4*)(hpT_b + ((size_t)d << 10) + m4 * 4);
    }
    #pragma unroll
    for (int i = 0; i < 4; i++) {
        int f = t + i * 256, d = f >> 4, m4 = f & 15;
        uint4 u = make_uint4(tf32c(pf[i].x), tf32c(pf[i].y), tf32c(pf[i].z), tf32c(pf[i].w));
        *(uint4*)(vt0 + d * VT_STRIDE + m4 * 4) = u;
    }
    __syncthreads();

    float c[8][4];
    #pragma unroll
    for (int j = 0; j < 8; j++)
        #pragma unroll
        for (int q = 0; q < 4; q++) c[j][q] = 0.f;
    float rs0 = 0.f, rs1 = 0.f;

    for (int mt = 0; mt < 16; mt++) {
        const uint32_t* V = (mt & 1) ? vt1 : vt0;
        if (mt < 15) {   // prefetch next tile into registers (overlaps compute)
            #pragma unroll
            for (int i = 0; i < 4; i++) {
                int f = t + i * 256, d = f >> 4, m4 = f & 15;
                pf[i] = *(const float4*)(hpT_b + ((size_t)d << 10) + (mt + 1) * 64 + m4 * 4);
            }
        }
        const float* eds = edst_s + mt * 64 + qm;
        #pragma unroll
        for (int ks = 0; ks < 8; ks++) {
            float ed0 = eds[ks * 8];
            float ed1 = eds[ks * 8 + 4];
            float x, w00, w10, w01, w11;
            x = es0 + ed0; x = fmaxf(x, ALPHA_ * x); w00 = ex2f(fmaf(x, LOG2E_, cb0));
            x = es1 + ed0; x = fmaxf(x, ALPHA_ * x); w10 = ex2f(fmaf(x, LOG2E_, cb1));
            x = es0 + ed1; x = fmaxf(x, ALPHA_ * x); w01 = ex2f(fmaf(x, LOG2E_, cb0));
            x = es1 + ed1; x = fmaxf(x, ALPHA_ * x); w11 = ex2f(fmaf(x, LOG2E_, cb1));
            uint32_t a0 = tf32c(w00), a1 = tf32c(w10), a2 = tf32c(w01), a3 = tf32c(w11);
            // rowsum of TRUNCATED weights -> consistent with mma numerator
            rs0 += __uint_as_float(a0) + __uint_as_float(a2);
            rs1 += __uint_as_float(a1) + __uint_as_float(a3);
            const uint32_t* bp = V + qr * VT_STRIDE + ks * 8 + qm;
            #pragma unroll
            for (int j = 0; j < 8; j++) {
                uint32_t b0 = bp[j * 8 * VT_STRIDE];
                uint32_t b1 = bp[j * 8 * VT_STRIDE + 4];
                mma_tf32(c[j][0], c[j][1], c[j][2], c[j][3], a0, a1, a2, a3, b0, b1);
            }
        }
        if (mt < 15) {
            uint32_t* Vn = (mt & 1) ? vt0 : vt1;
            #pragma unroll
            for (int i = 0; i < 4; i++) {
                int f = t + i * 256, d = f >> 4, m4 = f & 15;
                uint4 u = make_uint4(tf32c(pf[i].x), tf32c(pf[i].y), tf32c(pf[i].z), tf32c(pf[i].w));
                *(uint4*)(Vn + d * VT_STRIDE + m4 * 4) = u;
            }
        }
        __syncthreads();
    }

    // denominator: reduce over the 4 lanes sharing each row (qm axis)
    rs0 += __shfl_xor_sync(0xFFFFFFFFu, rs0, 1);
    rs0 += __shfl_xor_sync(0xFFFFFFFFu, rs0, 2);
    rs1 += __shfl_xor_sync(0xFFFFFFFFu, rs1, 1);
    rs1 += __shfl_xor_sync(0xFFFFFFFFu, rs1, 2);
    float inv0 = 1.0f / rs0, inv1 = 1.0f / rs1;

    // epilogue: normalize, residual, ELU, store (float2 per fragment pair)
    #pragma unroll
    for (int j = 0; j < 8; j++) {
        int d0 = 8 * j + 2 * qm;
        size_t base0 = ((size_t)(b * N_ + n0 + r)) * IND_ + head * HD_ + d0;
        float2 hv0 = *(const float2*)(h_in + base0);
        float ox = c[j][0] * inv0 + hv0.x;
        float oy = c[j][1] * inv0 + hv0.y;
        ox = ox > 0.f ? ox : expm1f(ox);
        oy = oy > 0.f ? oy : expm1f(oy);
        *(float2*)(out + base0) = make_float2(ox, oy);

        size_t base1 = base0 + (size_t)8 * IND_;
        float2 hv1 = *(const float2*)(h_in + base1);
        float oz = c[j][2] * inv1 + hv1.x;
        float ow = c[j][3] * inv1 + hv1.y;
        oz = oz > 0.f ? oz : expm1f(oz);
        ow = ow > 0.f ? ow : expm1f(ow);
        *(float2*)(out + base1) = make_float2(oz, ow);
    }
}

// ============================================================================
extern "C" void kernel_launch(void* const* d_in, const int* in_sizes, int n_in,
                              void* d_out, int out_size) {
    const float* h = (const float*)d_in[0];
    const float* W = (const float*)d_in[1];
    const float* a = (const float*)d_in[2];
    float* out = (float*)d_out;

    const int smemA = (64 * A_HS + 128 * 64) * 4;   // 65792 B
    cudaFuncSetAttribute(proj_kernel, cudaFuncAttributeMaxDynamicSharedMemorySize, smemA);
    cudaFuncSetAttribute(attn_kernel, cudaFuncAttributeMaxDynamicSharedMemorySize, SMEM_C);

    proj_kernel<<<dim3(256, 2), 256, smemA>>>(h, W, a);
    attn_kernel<<<dim3(8, 32), 256, SMEM_C>>>(h, out);
    (void)in_sizes; (void)n_in; (void)out_size;
}

// round 8
// speedup vs baseline: 4.0084x; 1.2317x over previous
#include <cuda_runtime.h>
#include <cuda_fp16.h>
#include <cstdint>

#define ALPHA_ 0.2f
#define LOG2E_ 1.4426950408889634f
#define B_    16
#define N_    1024
#define IND_  128
#define HEADS_ 2
#define HD_   64
#define BH_   (B_*HEADS_)

// Scratch: hpT16[bh][d][512 u32] = f16x2 pairs of hp along m, pair-permuted
// within each 16-m group: slot s even -> pair {s, s+1}; slot s odd (s=2q+1)
// -> pair {2q+8, 2q+9}  (exactly the m16n8k16 B-fragment order).
__device__ unsigned int g_hpT16[BH_ * HD_ * 512];
__device__ float g_esrc[BH_ * N_];
__device__ float g_edst[BH_ * N_];

// ---------------------------------------------------------------- helpers
__device__ __forceinline__ float ex2f(float x) {
    float y;
    asm("ex2.approx.ftz.f32 %0, %1;" : "=f"(y) : "f"(x));
    return y;
}
__device__ __forceinline__ uint32_t h2pack(float lo, float hi) {
    uint32_t r;
    asm("cvt.rn.f16x2.f32 %0, %1, %2;" : "=r"(r) : "f"(hi), "f"(lo));
    return r;
}
__device__ __forceinline__ void mma_tf32(float* c,
                                         uint32_t a0, uint32_t a1, uint32_t a2, uint32_t a3,
                                         uint32_t b0, uint32_t b1) {
    asm volatile(
        "mma.sync.aligned.m16n8k8.row.col.f32.tf32.tf32.f32 "
        "{%0,%1,%2,%3}, {%4,%5,%6,%7}, {%8,%9}, {%0,%1,%2,%3};"
        : "+f"(c[0]), "+f"(c[1]), "+f"(c[2]), "+f"(c[3])
        : "r"(a0), "r"(a1), "r"(a2), "r"(a3), "r"(b0), "r"(b1));
}
__device__ __forceinline__ void mma_f16(float* c,
                                        uint32_t a0, uint32_t a1, uint32_t a2, uint32_t a3,
                                        uint32_t b0, uint32_t b1) {
    asm volatile(
        "mma.sync.aligned.m16n8k16.row.col.f32.f16.f16.f32 "
        "{%0,%1,%2,%3}, {%4,%5,%6,%7}, {%8,%9}, {%0,%1,%2,%3};"
        : "+f"(c[0]), "+f"(c[1]), "+f"(c[2]), "+f"(c[3])
        : "r"(a0), "r"(a1), "r"(a2), "r"(a3), "r"(b0), "r"(b1));
}
__device__ __forceinline__ float wexp(float es, float ed, float cb) {
    float x = es + ed;
    float l = fmaxf(x, ALPHA_ * x);
    return ex2f(fmaf(l, LOG2E_, cb));
}

// ============================================================================
// Kernel A: hp = h @ W via tf32 mma.sync. CTA = 64 rows x 1 head, 128 threads
// (4 warps x 16 rows). Inputs nudged +0x1000 (truncate->round). Epilogue:
// e_src/e_dst from accumulators + hpT16 (f16, pair-permuted) via smem transpose.
// grid (256, 2).
// ============================================================================
__global__ void __launch_bounds__(128) proj_kernel(const float* __restrict__ h,
                                                   const float* __restrict__ W,
                                                   const float* __restrict__ a) {
    extern __shared__ float sm[];
    float* hA = sm;              // [64][136]
    float* WB = sm + 64 * 136;   // [128][68]
    float* T  = sm;              // epilogue reuse: [64 m][68 d]

    int t = threadIdx.x;
    int head = blockIdx.y;
    int r0 = blockIdx.x * 64;
    int b = r0 >> 10, nb = r0 & 1023;
    int bh = b * HEADS_ + head;

    // stage h tile (nudged fp32 -> tf32-round on truncation)
    #pragma unroll
    for (int i = 0; i < 16; i++) {
        int f = t + i * 128;
        int row = f >> 5, c4 = f & 31;
        uint4 v = *(const uint4*)(h + (size_t)(r0 + row) * IND_ + c4 * 4);
        v.x += 0x1000u; v.y += 0x1000u; v.z += 0x1000u; v.w += 0x1000u;
        *(uint4*)(hA + row * 136 + c4 * 4) = v;
    }
    // stage W[head] tile [k][d]
    #pragma unroll
    for (int i = 0; i < 16; i++) {
        int f = t + i * 128;
        int k = f >> 4, d4 = f & 15;
        uint4 v = *(const uint4*)(W + (size_t)head * (IND_ * HD_) + k * HD_ + d4 * 4);
        v.x += 0x1000u; v.y += 0x1000u; v.z += 0x1000u; v.w += 0x1000u;
        *(uint4*)(WB + k * 68 + d4 * 4) = v;
    }
    __syncthreads();

    int w = t >> 5, lane = t & 31, qr = lane >> 2, qm = lane & 3;
    int rA = w * 16 + qr;

    float c[8][4];
    #pragma unroll
    for (int j = 0; j < 8; j++)
        #pragma unroll
        for (int q = 0; q < 4; q++) c[j][q] = 0.f;

    #pragma unroll
    for (int ks = 0; ks < 16; ks++) {
        int k0 = ks * 8;
        uint32_t a0 = __float_as_uint(hA[rA * 136 + k0 + qm]);
        uint32_t a1 = __float_as_uint(hA[(rA + 8) * 136 + k0 + qm]);
        uint32_t a2 = __float_as_uint(hA[rA * 136 + k0 + qm + 4]);
        uint32_t a3 = __float_as_uint(hA[(rA + 8) * 136 + k0 + qm + 4]);
        const float* b0r = WB + (k0 + qm) * 68 + qr;
        const float* b1r = WB + (k0 + qm + 4) * 68 + qr;
        #pragma unroll
        for (int j = 0; j < 8; j++) {
            mma_tf32(c[j], a0, a1, a2, a3,
                     __float_as_uint(b0r[8 * j]), __float_as_uint(b1r[8 * j]));
        }
    }

    // e_src / e_dst dots from accumulators
    {
        const float* ah = a + head * (2 * HD_);
        float ps0 = 0.f, ps1 = 0.f, pd0 = 0.f, pd1 = 0.f;
        #pragma unroll
        for (int j = 0; j < 8; j++) {
            float2 as = *(const float2*)(ah + 8 * j + 2 * qm);
            float2 ad = *(const float2*)(ah + HD_ + 8 * j + 2 * qm);
            ps0 += c[j][0] * as.x + c[j][1] * as.y;
            ps1 += c[j][2] * as.x + c[j][3] * as.y;
            pd0 += c[j][0] * ad.x + c[j][1] * ad.y;
            pd1 += c[j][2] * ad.x + c[j][3] * ad.y;
        }
        #pragma unroll
        for (int o = 1; o <= 2; o <<= 1) {
            ps0 += __shfl_xor_sync(0xFFFFFFFFu, ps0, o);
            ps1 += __shfl_xor_sync(0xFFFFFFFFu, ps1, o);
            pd0 += __shfl_xor_sync(0xFFFFFFFFu, pd0, o);
            pd1 += __shfl_xor_sync(0xFFFFFFFFu, pd1, o);
        }
        if (qm == 0) {
            int n = nb + rA;
            g_esrc[(size_t)bh * N_ + n] = ps0;
            g_edst[(size_t)bh * N_ + n] = pd0;
            g_esrc[(size_t)bh * N_ + n + 8] = ps1;
            g_edst[(size_t)bh * N_ + n + 8] = pd1;
        }
    }

    __syncthreads();   // all warps done with hA/WB
    // write c -> T[m][d] (stride 68)
    #pragma unroll
    for (int j = 0; j < 8; j++) {
        *(float2*)(T + rA * 68 + 8 * j + 2 * qm)       = make_float2(c[j][0], c[j][1]);
        *(float2*)(T + (rA + 8) * 68 + 8 * j + 2 * qm) = make_float2(c[j][2], c[j][3]);
    }
    __syncthreads();

    // pack to f16 pairs with the attn B-fragment permutation, store coalesced.
    // FIX (R7 bug): m-offset within the [bh][d] row is the tile index WITHIN
    // this bh -> (nb >> 6) * 32 == (blockIdx.x & 15) * 32, NOT blockIdx.x * 32.
    {
        int d = t >> 1;
        int mtile = (nb >> 6) * 32;
        #pragma unroll
        for (int i = 0; i < 4; i++) {
            int q = (t & 1) * 4 + i;     // uint4 index within row (8 per 64-m row)
            uint32_t u[4];
            #pragma unroll
            for (int e = 0; e < 4; e++) {
                int idx = 4 * q + e;          // u32 slot within row (32 total)
                int g = idx >> 3;             // 16-m group
                int dd = idx & 7;             // slot within group
                int p = (dd & 1) ? 4 + (dd >> 1) : (dd >> 1);   // pair index
                int ml = g * 16 + 2 * p;
                u[e] = h2pack(T[ml * 68 + d], T[(ml + 1) * 68 + d]);
            }
            *(uint4*)(g_hpT16 + ((size_t)bh * HD_ + d) * 512 + mtile + 4 * q) =
                make_uint4(u[0], u[1], u[2], u[3]);
        }
    }
}

// ============================================================================
// Kernel C: fp16 mma.sync attention. CTA = 64 n rows, 256 threads = 8 warps:
// 4 row-groups x 2 m-splits (512 m each). Denominator via ones-column MMA.
// V tiles (32 m per split) double-buffered in smem, stride 24 u32. grid (16,32).
// ============================================================================
#define SB_V     0                     // [2 s][2 buf][64 d][24 u32] = 24576 B
#define SB_EDP   24576                 // permuted e_dst, 4096 B
#define SB_ESRC  28672                 // 256 B
#define SB_RED   28928                 // 64 B
#define SMEM_C   28992
#define CB_STRIDE 38                   // combine buffer stride (floats)

__global__ void __launch_bounds__(256) attn_kernel(const float* __restrict__ h_in,
                                                   float* __restrict__ out) {
    extern __shared__ char smc[];
    uint32_t* VB   = (uint32_t*)(smc + SB_V);
    float* edp     = (float*)(smc + SB_EDP);
    float* esrc_s  = (float*)(smc + SB_ESRC);
    float* red     = (float*)(smc + SB_RED);
    float* cbuf    = (float*)(smc + SB_V);   // epilogue reuse (19456 B < 24576)

    int t = threadIdx.x, w = t >> 5, lane = t & 31;
    int qr = lane >> 2, qm = lane & 3;
    int ws = w >> 2, rg = w & 3;
    int bh = blockIdx.y, b = bh >> 1, head = bh & 1;
    int n0 = blockIdx.x * 64;

    // staging map (constant per thread): warps 0-3 stage split 0, 4-7 split 1
    int ss = t >> 7, sd = (t >> 1) & 63, sg = t & 1;
    const uint32_t* srcu = g_hpT16 + ((size_t)bh * HD_ + sd) * 512 + ss * 256 + sg * 8;
    uint32_t* dst0 = VB + (ss * 2) * 1536 + sd * 24 + sg * 8;
    uint32_t* dst1 = VB + (ss * 2 + 1) * 1536 + sd * 24 + sg * 8;

    // e_dst load + permuted store + block max; e_src rows
    float4 ed4 = *(const float4*)(g_edst + (size_t)bh * N_ + t * 4);
    {
        float lm = fmaxf(fmaxf(ed4.x, ed4.y), fmaxf(ed4.z, ed4.w));
        #pragma unroll
        for (int o = 16; o; o >>= 1) lm = fmaxf(lm, __shfl_xor_sync(0xFFFFFFFFu, lm, o));
        if (lane == 0) red[w] = lm;
        float edv[4] = {ed4.x, ed4.y, ed4.z, ed4.w};
        #pragma unroll
        for (int e = 0; e < 4; e++) {
            int m = 4 * t + e;
            int g = m >> 4, q = m & 15;
            int dsti = (q < 8) ? ((q >> 1) * 4 + (q & 1))
                               : ((q - 8) >> 1) * 4 + 2 + (q & 1);
            edp[g * 16 + dsti] = edv[e];
        }
    }
    if (t < 64) esrc_s[t] = g_esrc[(size_t)bh * N_ + n0 + t];

    // stage V tile 0
    {
        uint4 p0 = *(const uint4*)(srcu);
        uint4 p1 = *(const uint4*)(srcu + 4);
        *(uint4*)(dst0) = p0;
        *(uint4*)(dst0 + 4) = p1;
    }
    __syncthreads();
    if (t == 0) {
        float m = red[0];
        #pragma unroll
        for (int i = 1; i < 8; i++) m = fmaxf(m, red[i]);
        red[0] = m;
    }
    __syncthreads();
    float Mx = red[0];

    int r = rg * 16 + qr;
    float es0 = esrc_s[r], es1 = esrc_s[r + 8];
    float x0 = es0 + Mx, x1 = es1 + Mx;
    float cb0 = -fmaxf(x0, ALPHA_ * x0) * LOG2E_;
    float cb1 = -fmaxf(x1, ALPHA_ * x1) * LOG2E_;

    float c[9][4];
    #pragma unroll
    for (int j = 0; j < 9; j++)
        #pragma unroll
        for (int q = 0; q < 4; q++) c[j][q] = 0.f;

    const uint32_t ONE2 = 0x3C003C00u;

    for (int mt = 0; mt < 16; mt++) {
        uint4 p0, p1;
        if (mt < 15) {
            p0 = *(const uint4*)(srcu + (mt + 1) * 16);
            p1 = *(const uint4*)(srcu + (mt + 1) * 16 + 4);
        }
        const uint32_t* Vb = VB + (ws * 2 + (mt & 1)) * 1536;
        #pragma unroll
        for (int ks = 0; ks < 2; ks++) {
            int kk16 = ws * 32 + mt * 2 + ks;
            float4 e4 = *(const float4*)(edp + kk16 * 16 + 4 * qm);
            uint32_t a0 = h2pack(wexp(es0, e4.x, cb0), wexp(es0, e4.y, cb0));
            uint32_t a1 = h2pack(wexp(es1, e4.x, cb1), wexp(es1, e4.y, cb1));
            uint32_t a2 = h2pack(wexp(es0, e4.z, cb0), wexp(es0, e4.w, cb0));
            uint32_t a3 = h2pack(wexp(es1, e4.z, cb1), wexp(es1, e4.w, cb1));
            const uint32_t* bp = Vb + ks * 8 + 2 * qm;
            #pragma unroll
            for (int j = 0; j < 8; j++) {
                uint2 bb = *(const uint2*)(bp + (qr + 8 * j) * 24);
                mma_f16(c[j], a0, a1, a2, a3, bb.x, bb.y);
            }
            mma_f16(c[8], a0, a1, a2, a3, ONE2, ONE2);   // rowsum (denominator)
        }
        if (mt < 15) {
            uint32_t* du = ((mt + 1) & 1) ? dst1 : dst0;
            *(uint4*)(du) = p0;
            *(uint4*)(du + 4) = p1;
        }
        __syncthreads();
    }

    // combine m-splits: warps 4-7 export, warps 0-3 add + epilogue
    if (ws == 1) {
        float* cb = cbuf + (rg * 32 + lane) * CB_STRIDE;
        #pragma unroll
        for (int j = 0; j < 9; j++) {
            *(float2*)(cb + 4 * j)     = make_float2(c[j][0], c[j][1]);
            *(float2*)(cb + 4 * j + 2) = make_float2(c[j][2], c[j][3]);
        }
    }
    __syncthreads();
    if (ws == 0) {
        const float* cb = cbuf + (rg * 32 + lane) * CB_STRIDE;
        #pragma unroll
        for (int j = 0; j < 9; j++) {
            float2 p0 = *(const float2*)(cb + 4 * j);
            float2 p1 = *(const float2*)(cb + 4 * j + 2);
            c[j][0] += p0.x; c[j][1] += p0.y; c[j][2] += p1.x; c[j][3] += p1.y;
        }
        float inv0 = 1.0f / c[8][0];
        float inv1 = 1.0f / c[8][2];
        int n_row = n0 + r;
        #pragma unroll
        for (int j = 0; j < 8; j++) {
            int d0 = 8 * j + 2 * qm;
            size_t base0 = ((size_t)(b * N_ + n_row)) * IND_ + head * HD_ + d0;
            float2 hv0 = *(const float2*)(h_in + base0);
            float ox = c[j][0] * inv0 + hv0.x;
            float oy = c[j][1] * inv0 + hv0.y;
            ox = ox > 0.f ? ox : expm1f(ox);
            oy = oy > 0.f ? oy : expm1f(oy);
            *(float2*)(out + base0) = make_float2(ox, oy);

            size_t base1 = base0 + (size_t)8 * IND_;
            float2 hv1 = *(const float2*)(h_in + base1);
            float oz = c[j][2] * inv1 + hv1.x;
            float ow = c[j][3] * inv1 + hv1.y;
            oz = oz > 0.f ? oz : expm1f(oz);
            ow = ow > 0.f ? ow : expm1f(ow);
            *(float2*)(out + base1) = make_float2(oz, ow);
        }
    }
}

// ============================================================================
extern "C" void kernel_launch(void* const* d_in, const int* in_sizes, int n_in,
                              void* d_out, int out_size) {
    const float* h = (const float*)d_in[0];
    const float* W = (const float*)d_in[1];
    const float* a = (const float*)d_in[2];
    float* out = (float*)d_out;

    const int smemA = (64 * 136 + 128 * 68) * 4;   // 69632 B
    cudaFuncSetAttribute(proj_kernel, cudaFuncAttributeMaxDynamicSharedMemorySize, smemA);
    cudaFuncSetAttribute(attn_kernel, cudaFuncAttributeMaxDynamicSharedMemorySize, SMEM_C);

    proj_kernel<<<dim3(256, 2), 128, smemA>>>(h, W, a);
    attn_kernel<<<dim3(16, 32), 256, SMEM_C>>>(h, out);
    (void)in_sizes; (void)n_in; (void)out_size;
}

// round 9
// speedup vs baseline: 5.3898x; 1.3446x over previous
#include <cuda_runtime.h>
#include <cuda_fp16.h>
#include <cstdint>

#define ALPHA_ 0.2f
#define LOG2E_ 1.4426950408889634f
#define B_    16
#define N_    1024
#define IND_  128
#define HEADS_ 2
#define HD_   64
#define BH_   (B_*HEADS_)

// Scratch. g_hpT16 layout (uint2 units): [bh][split(2)][mt(16)][ks(2)][j(8)][lane(32)]
// uint2 content for (d=8j+qr, qm): .x = f16x2{V[m0][d], V[m0+1][d]},
// .y = f16x2{V[m0+8][d], V[m0+9][d]}, m0 = split*512 + mt*32 + ks*16 + 2qm.
// This is EXACTLY the m16n8k16 B-fragment register pair per lane.
__device__ __align__(16) unsigned int g_hpT16[BH_ * HD_ * 512];
__device__ float g_esrc[BH_ * N_];
__device__ float g_edst[BH_ * N_];

// ---------------------------------------------------------------- helpers
__device__ __forceinline__ float ex2f(float x) {
    float y;
    asm("ex2.approx.ftz.f32 %0, %1;" : "=f"(y) : "f"(x));
    return y;
}
__device__ __forceinline__ uint32_t h2pack(float lo, float hi) {
    uint32_t r;
    asm("cvt.rn.f16x2.f32 %0, %1, %2;" : "=r"(r) : "f"(hi), "f"(lo));
    return r;
}
__device__ __forceinline__ uint32_t smem_u32(const void* p) {
    uint32_t a;
    asm("{ .reg .u64 t; cvta.to.shared.u64 t, %1; cvt.u32.u64 %0, t; }" : "=r"(a) : "l"(p));
    return a;
}
__device__ __forceinline__ void cp16(uint32_t dst, const void* src) {
    asm volatile("cp.async.cg.shared.global [%0], [%1], 16;" :: "r"(dst), "l"(src) : "memory");
}
#define CP_COMMIT() asm volatile("cp.async.commit_group;" ::: "memory")
#define CP_WAIT(n)  asm volatile("cp.async.wait_group %0;" :: "n"(n) : "memory")

__device__ __forceinline__ void mma_tf32(float* c,
                                         uint32_t a0, uint32_t a1, uint32_t a2, uint32_t a3,
                                         uint32_t b0, uint32_t b1) {
    asm volatile(
        "mma.sync.aligned.m16n8k8.row.col.f32.tf32.tf32.f32 "
        "{%0,%1,%2,%3}, {%4,%5,%6,%7}, {%8,%9}, {%0,%1,%2,%3};"
        : "+f"(c[0]), "+f"(c[1]), "+f"(c[2]), "+f"(c[3])
        : "r"(a0), "r"(a1), "r"(a2), "r"(a3), "r"(b0), "r"(b1));
}
__device__ __forceinline__ void mma_f16(float* c,
                                        uint32_t a0, uint32_t a1, uint32_t a2, uint32_t a3,
                                        uint32_t b0, uint32_t b1) {
    asm volatile(
        "mma.sync.aligned.m16n8k16.row.col.f32.f16.f16.f32 "
        "{%0,%1,%2,%3}, {%4,%5,%6,%7}, {%8,%9}, {%0,%1,%2,%3};"
        : "+f"(c[0]), "+f"(c[1]), "+f"(c[2]), "+f"(c[3])
        : "r"(a0), "r"(a1), "r"(a2), "r"(a3), "r"(b0), "r"(b1));
}
// 4-op exp in log2 domain: eL = ed*log2e; p = es*L + cb; q = 0.2*es*L + cb
__device__ __forceinline__ float wexp4(float eL, float p, float q) {
    float t = p + eL;
    float u = fmaf(ALPHA_, eL, q);
    return ex2f(fmaxf(t, u));
}

// ============================================================================
// Kernel A: hp = h @ W via tf32 mma.sync. CTA = 128 rows x 1 head, 256 thr
// (8 warps x 16 rows). +0x1000 nudge = round-to-nearest tf32. Epilogue:
// e_src/e_dst + fragment-ordered f16 V writes. grid (128, 2).
// ============================================================================
__global__ void __launch_bounds__(256) proj_kernel(const float* __restrict__ h,
                                                   const float* __restrict__ W,
                                                   const float* __restrict__ a) {
    extern __shared__ float sm[];
    float* hA = sm;               // [128][136]
    float* WB = sm + 128 * 136;   // [128][68]
    float* T  = sm;               // epilogue reuse: [128 m][68 d]

    int t = threadIdx.x;
    int head = blockIdx.y;
    int r0 = blockIdx.x * 128;
    int b = r0 >> 10, nb = r0 & 1023;
    int bh = b * HEADS_ + head;

    #pragma unroll
    for (int i = 0; i < 16; i++) {
        int f = t + i * 256;
        int row = f >> 5, c4 = f & 31;
        uint4 v = *(const uint4*)(h + (size_t)(r0 + row) * IND_ + c4 * 4);
        v.x += 0x1000u; v.y += 0x1000u; v.z += 0x1000u; v.w += 0x1000u;
        *(uint4*)(hA + row * 136 + c4 * 4) = v;
    }
    #pragma unroll
    for (int i = 0; i < 8; i++) {
        int f = t + i * 256;
        int k = f >> 4, d4 = f & 15;
        uint4 v = *(const uint4*)(W + (size_t)head * (IND_ * HD_) + k * HD_ + d4 * 4);
        v.x += 0x1000u; v.y += 0x1000u; v.z += 0x1000u; v.w += 0x1000u;
        *(uint4*)(WB + k * 68 + d4 * 4) = v;
    }
    __syncthreads();

    int w = t >> 5, lane = t & 31, qr = lane >> 2, qm = lane & 3;
    int rA = w * 16 + qr;

    float c[8][4];
    #pragma unroll
    for (int j = 0; j < 8; j++)
        #pragma unroll
        for (int q = 0; q < 4; q++) c[j][q] = 0.f;

    #pragma unroll
    for (int ks = 0; ks < 16; ks++) {
        int k0 = ks * 8;
        uint32_t a0 = __float_as_uint(hA[rA * 136 + k0 + qm]);
        uint32_t a1 = __float_as_uint(hA[(rA + 8) * 136 + k0 + qm]);
        uint32_t a2 = __float_as_uint(hA[rA * 136 + k0 + qm + 4]);
        uint32_t a3 = __float_as_uint(hA[(rA + 8) * 136 + k0 + qm + 4]);
        const float* b0r = WB + (k0 + qm) * 68 + qr;
        const float* b1r = WB + (k0 + qm + 4) * 68 + qr;
        #pragma unroll
        for (int j = 0; j < 8; j++) {
            mma_tf32(c[j], a0, a1, a2, a3,
                     __float_as_uint(b0r[8 * j]), __float_as_uint(b1r[8 * j]));
        }
    }

    // e_src / e_dst dots from accumulators
    {
        const float* ah = a + head * (2 * HD_);
        float ps0 = 0.f, ps1 = 0.f, pd0 = 0.f, pd1 = 0.f;
        #pragma unroll
        for (int j = 0; j < 8; j++) {
            float2 as = *(const float2*)(ah + 8 * j + 2 * qm);
            float2 ad = *(const float2*)(ah + HD_ + 8 * j + 2 * qm);
            ps0 += c[j][0] * as.x + c[j][1] * as.y;
            ps1 += c[j][2] * as.x + c[j][3] * as.y;
            pd0 += c[j][0] * ad.x + c[j][1] * ad.y;
            pd1 += c[j][2] * ad.x + c[j][3] * ad.y;
        }
        #pragma unroll
        for (int o = 1; o <= 2; o <<= 1) {
            ps0 += __shfl_xor_sync(0xFFFFFFFFu, ps0, o);
            ps1 += __shfl_xor_sync(0xFFFFFFFFu, ps1, o);
            pd0 += __shfl_xor_sync(0xFFFFFFFFu, pd0, o);
            pd1 += __shfl_xor_sync(0xFFFFFFFFu, pd1, o);
        }
        if (qm == 0) {
            int n = nb + rA;
            g_esrc[(size_t)bh * N_ + n] = ps0;
            g_edst[(size_t)bh * N_ + n] = pd0;
            g_esrc[(size_t)bh * N_ + n + 8] = ps1;
            g_edst[(size_t)bh * N_ + n + 8] = pd1;
        }
    }

    __syncthreads();
    #pragma unroll
    for (int j = 0; j < 8; j++) {
        *(float2*)(T + rA * 68 + 8 * j + 2 * qm)       = make_float2(c[j][0], c[j][1]);
        *(float2*)(T + (rA + 8) * 68 + 8 * j + 2 * qm) = make_float2(c[j][2], c[j][3]);
    }
    __syncthreads();

    // fragment-ordered f16 pack: 2048 uint2 per CTA, 8 per thread
    {
        int s = nb >> 9;
        int mt0 = (nb & 511) >> 5;
        uint2* gbase = (uint2*)g_hpT16 + ((size_t)(bh * 2 + s)) * 8192 + mt0 * 512;
        #pragma unroll
        for (int i = 0; i < 8; i++) {
            int cidx = t + i * 256;
            int mtl = cidx >> 9, ks = (cidx >> 8) & 1, j = (cidx >> 5) & 7;
            int ln = cidx & 31, lqr = ln >> 2, lqm = ln & 3;
            int d = 8 * j + lqr;
            int m0 = mtl * 32 + ks * 16 + 2 * lqm;
            uint2 u;
            u.x = h2pack(T[m0 * 68 + d], T[(m0 + 1) * 68 + d]);
            u.y = h2pack(T[(m0 + 8) * 68 + d], T[(m0 + 9) * 68 + d]);
            gbase[mtl * 512 + ks * 256 + j * 32 + ln] = u;
        }
    }
}

// ============================================================================
// Kernel C: fp16 mma attention. CTA = 64 n rows, 256 thr = 8 warps (4 row-
// groups x 2 m-splits of 512 m). cp.async triple-buffered V (frag-ordered,
// conflict-free LDS.64). 4-op exp. Ones-column MMA denominator. grid (16,32),
// 4 CTAs/SM -> single wave.
// ============================================================================
#define SB_V     0                    // 3 stages x 2 splits x 4096 B = 24576
#define SB_EDP   24576                // e_dst * log2e, permuted: 4096 B
#define SB_ESRC  28672                // e_src * log2e: 256 B
#define SB_RED   28928                // 64 B
#define SMEM_C   28992
#define CB_STRIDE 38

__global__ void __launch_bounds__(256, 4) attn_kernel(const float* __restrict__ h_in,
                                                      float* __restrict__ out) {
    extern __shared__ char smc[];
    const uint32_t sb = smem_u32(smc);
    float* edp    = (float*)(smc + SB_EDP);
    float* esrc_s = (float*)(smc + SB_ESRC);
    float* red    = (float*)(smc + SB_RED);
    float* cbuf   = (float*)(smc + SB_V);   // epilogue reuse (19456 < 24576)

    int t = threadIdx.x, w = t >> 5, lane = t & 31;
    int qr = lane >> 2, qm = lane & 3;
    int ws = w >> 2, rg = w & 3;
    int bh = blockIdx.y, b = bh >> 1, head = bh & 1;
    int n0 = blockIdx.x * 64;

    // cp.async staging map: thread covers split ss, 32B per mt
    int ss = t >> 7, i128 = t & 127;
    const char* gsrc = (const char*)((const uint2*)g_hpT16 +
                       ((size_t)(bh * 2 + ss)) * 8192 + i128 * 4);
    uint32_t sdst = sb + SB_V + ss * 4096 + i128 * 32;

    // stage 0 of V (mt=0)
    cp16(sdst, gsrc);
    cp16(sdst + 16, gsrc + 16);
    CP_COMMIT();

    // e_dst -> edp (scaled by log2e, fragment-permuted) + block max (scaled)
    float4 ed4 = *(const float4*)(g_edst + (size_t)bh * N_ + t * 4);
    ed4.x *= LOG2E_; ed4.y *= LOG2E_; ed4.z *= LOG2E_; ed4.w *= LOG2E_;
    {
        float lm = fmaxf(fmaxf(ed4.x, ed4.y), fmaxf(ed4.z, ed4.w));
        #pragma unroll
        for (int o = 16; o; o >>= 1) lm = fmaxf(lm, __shfl_xor_sync(0xFFFFFFFFu, lm, o));
        if (lane == 0) red[w] = lm;
        float edv[4] = {ed4.x, ed4.y, ed4.z, ed4.w};
        #pragma unroll
        for (int e = 0; e < 4; e++) {
            int m = 4 * t + e;
            int g = m >> 4, q = m & 15;
            int dsti = (q < 8) ? ((q >> 1) * 4 + (q & 1))
                               : ((q - 8) >> 1) * 4 + 2 + (q & 1);
            edp[g * 16 + dsti] = edv[e];
        }
    }
    if (t < 64) esrc_s[t] = g_esrc[(size_t)bh * N_ + n0 + t] * LOG2E_;
    __syncthreads();
    if (t == 0) {
        float m = red[0];
        #pragma unroll
        for (int i = 1; i < 8; i++) m = fmaxf(m, red[i]);
        red[0] = m;
    }
    __syncthreads();
    float MxL = red[0];

    // per-thread row constants (log2 domain)
    int r = rg * 16 + qr;
    float esL0 = esrc_s[r], esL1 = esrc_s[r + 8];
    float x0 = esL0 + MxL, x1 = esL1 + MxL;
    float cb0 = -fmaxf(x0, ALPHA_ * x0);
    float cb1 = -fmaxf(x1, ALPHA_ * x1);
    float p0 = esL0 + cb0, q0 = fmaf(ALPHA_, esL0, cb0);
    float p1 = esL1 + cb1, q1 = fmaf(ALPHA_, esL1, cb1);

    float c[9][4];
    #pragma unroll
    for (int j = 0; j < 9; j++)
        #pragma unroll
        for (int q = 0; q < 4; q++) c[j][q] = 0.f;

    const uint32_t ONE2 = 0x3C003C00u;

    for (int mt = 0; mt < 16; mt++) {
        int st = mt % 3;
        if (mt < 15) {
            int stn = (mt + 1) % 3;
            const char* gs = gsrc + (size_t)(mt + 1) * 4096;
            uint32_t sd = sb + SB_V + stn * 8192 + ss * 4096 + i128 * 32;
            cp16(sd, gs);
            cp16(sd + 16, gs + 16);
            CP_COMMIT();
            CP_WAIT(1);
        } else {
            CP_WAIT(0);
        }
        __syncthreads();

        const uint2* Vb2 = (const uint2*)(smc + SB_V + st * 8192 + ws * 4096);
        // A-fragments for both k16 steps first (exp latency overlaps MMA below)
        uint32_t af[2][4];
        #pragma unroll
        for (int ks = 0; ks < 2; ks++) {
            int kk16 = ws * 32 + mt * 2 + ks;
            float4 e4 = *(const float4*)(edp + kk16 * 16 + 4 * qm);
            af[ks][0] = h2pack(wexp4(e4.x, p0, q0), wexp4(e4.y, p0, q0));
            af[ks][1] = h2pack(wexp4(e4.x, p1, q1), wexp4(e4.y, p1, q1));
            af[ks][2] = h2pack(wexp4(e4.z, p0, q0), wexp4(e4.w, p0, q0));
            af[ks][3] = h2pack(wexp4(e4.z, p1, q1), wexp4(e4.w, p1, q1));
        }
        #pragma unroll
        for (int ks = 0; ks < 2; ks++) {
            const uint2* bp = Vb2 + ks * 256 + lane;
            #pragma unroll
            for (int j = 0; j < 8; j++) {
                uint2 bb = bp[j * 32];
                mma_f16(c[j], af[ks][0], af[ks][1], af[ks][2], af[ks][3], bb.x, bb.y);
            }
            mma_f16(c[8], af[ks][0], af[ks][1], af[ks][2], af[ks][3], ONE2, ONE2);
        }
    }
    __syncthreads();   // all V reads done before cbuf overlays SB_V

    // combine m-splits: warps 4-7 export, warps 0-3 add + epilogue
    if (ws == 1) {
        float* cb = cbuf + (rg * 32 + lane) * CB_STRIDE;
        #pragma unroll
        for (int j = 0; j < 9; j++) {
            *(float2*)(cb + 4 * j)     = make_float2(c[j][0], c[j][1]);
            *(float2*)(cb + 4 * j + 2) = make_float2(c[j][2], c[j][3]);
        }
    }
    __syncthreads();
    if (ws == 0) {
        const float* cb = cbuf + (rg * 32 + lane) * CB_STRIDE;
        #pragma unroll
        for (int j = 0; j < 9; j++) {
            float2 pa = *(const float2*)(cb + 4 * j);
            float2 pb = *(const float2*)(cb + 4 * j + 2);
            c[j][0] += pa.x; c[j][1] += pa.y; c[j][2] += pb.x; c[j][3] += pb.y;
        }
        float inv0 = 1.0f / c[8][0];
        float inv1 = 1.0f / c[8][2];
        int n_row = n0 + r;
        #pragma unroll
        for (int j = 0; j < 8; j++) {
            int d0 = 8 * j + 2 * qm;
            size_t base0 = ((size_t)(b * N_ + n_row)) * IND_ + head * HD_ + d0;
            float2 hv0 = *(const float2*)(h_in + base0);
            float ox = c[j][0] * inv0 + hv0.x;
            float oy = c[j][1] * inv0 + hv0.y;
            ox = ox > 0.f ? ox : expm1f(ox);
            oy = oy > 0.f ? oy : expm1f(oy);
            *(float2*)(out + base0) = make_float2(ox, oy);

            size_t base1 = base0 + (size_t)8 * IND_;
            float2 hv1 = *(const float2*)(h_in + base1);
            float oz = c[j][2] * inv1 + hv1.x;
            float ow = c[j][3] * inv1 + hv1.y;
            oz = oz > 0.f ? oz : expm1f(oz);
            ow = ow > 0.f ? ow : expm1f(ow);
            *(float2*)(out + base1) = make_float2(oz, ow);
        }
    }
}

// ============================================================================
extern "C" void kernel_launch(void* const* d_in, const int* in_sizes, int n_in,
                              void* d_out, int out_size) {
    const float* h = (const float*)d_in[0];
    const float* W = (const float*)d_in[1];
    const float* a = (const float*)d_in[2];
    float* out = (float*)d_out;

    const int smemA = (128 * 136 + 128 * 68) * 4;   // 104448 B
    cudaFuncSetAttribute(proj_kernel, cudaFuncAttributeMaxDynamicSharedMemorySize, smemA);
    cudaFuncSetAttribute(attn_kernel, cudaFuncAttributeMaxDynamicSharedMemorySize, SMEM_C);

    proj_kernel<<<dim3(128, 2), 256, smemA>>>(h, W, a);
    attn_kernel<<<dim3(16, 32), 256, SMEM_C>>>(h, out);
    (void)in_sizes; (void)n_in; (void)out_size;
}

// round 10
// speedup vs baseline: 5.4161x; 1.0049x over previous
#include <cuda_runtime.h>
#include <cuda_fp16.h>
#include <cstdint>

#define ALPHA_ 0.2f
#define LOG2E_ 1.4426950408889634f
#define B_    16
#define N_    1024
#define IND_  128
#define HEADS_ 2
#define HD_   64
#define BH_   (B_*HEADS_)

// Scratch. g_hpT16 layout (uint2 units): [bh][split(2)][mt(16)][ks(2)][j(8)][lane(32)]
// uint2 per (d=8j+qr, qm): .x = f16x2{V[m0][d], V[m0+1][d]},
// .y = f16x2{V[m0+8][d], V[m0+9][d]}, m0 = split*512 + mt*32 + ks*16 + 2qm.
// (exactly the m16n8k16 B-fragment register pair per lane)
__device__ __align__(16) unsigned int g_hpT16[BH_ * HD_ * 512];
__device__ float g_esrc[BH_ * N_];
__device__ float g_edst[BH_ * N_];

// ---------------------------------------------------------------- helpers
__device__ __forceinline__ float ex2f(float x) {
    float y;
    asm("ex2.approx.ftz.f32 %0, %1;" : "=f"(y) : "f"(x));
    return y;
}
__device__ __forceinline__ uint32_t h2pack(float lo, float hi) {
    uint32_t r;
    asm("cvt.rn.f16x2.f32 %0, %1, %2;" : "=r"(r) : "f"(hi), "f"(lo));
    return r;
}
__device__ __forceinline__ uint32_t smem_u32(const void* p) {
    uint32_t a;
    asm("{ .reg .u64 t; cvta.to.shared.u64 t, %1; cvt.u32.u64 %0, t; }" : "=r"(a) : "l"(p));
    return a;
}
__device__ __forceinline__ void cp16(uint32_t dst, const void* src) {
    asm volatile("cp.async.cg.shared.global [%0], [%1], 16;" :: "r"(dst), "l"(src) : "memory");
}
#define CP_COMMIT() asm volatile("cp.async.commit_group;" ::: "memory")
#define CP_WAIT(n)  asm volatile("cp.async.wait_group %0;" :: "n"(n) : "memory")

__device__ __forceinline__ void mma_tf32(float* c,
                                         uint32_t a0, uint32_t a1, uint32_t a2, uint32_t a3,
                                         uint32_t b0, uint32_t b1) {
    asm volatile(
        "mma.sync.aligned.m16n8k8.row.col.f32.tf32.tf32.f32 "
        "{%0,%1,%2,%3}, {%4,%5,%6,%7}, {%8,%9}, {%0,%1,%2,%3};"
        : "+f"(c[0]), "+f"(c[1]), "+f"(c[2]), "+f"(c[3])
        : "r"(a0), "r"(a1), "r"(a2), "r"(a3), "r"(b0), "r"(b1));
}
__device__ __forceinline__ void mma_f16(float* c,
                                        uint32_t a0, uint32_t a1, uint32_t a2, uint32_t a3,
                                        uint32_t b0, uint32_t b1) {
    asm volatile(
        "mma.sync.aligned.m16n8k16.row.col.f32.f16.f16.f32 "
        "{%0,%1,%2,%3}, {%4,%5,%6,%7}, {%8,%9}, {%0,%1,%2,%3};"
        : "+f"(c[0]), "+f"(c[1]), "+f"(c[2]), "+f"(c[3])
        : "r"(a0), "r"(a1), "r"(a2), "r"(a3), "r"(b0), "r"(b1));
}
// 4-op exp in log2 domain: eL = ed*log2e; p = esL + cb; q = 0.2*esL + cb
__device__ __forceinline__ float wexp4(float eL, float p, float q) {
    float t = p + eL;
    float u = fmaf(ALPHA_, eL, q);
    return ex2f(fmaxf(t, u));
}

// ============================================================================
// Kernel A: hp = h @ W via tf32 mma.sync. CTA = 128 rows x 1 head, 256 thr.
// +0x1000 nudge = round-to-nearest tf32. Epilogue: e_src/e_dst + fragment-
// ordered f16 V. grid (128, 2).  (unchanged from R9)
// ============================================================================
__global__ void __launch_bounds__(256) proj_kernel(const float* __restrict__ h,
                                                   const float* __restrict__ W,
                                                   const float* __restrict__ a) {
    extern __shared__ float sm[];
    float* hA = sm;               // [128][136]
    float* WB = sm + 128 * 136;   // [128][68]
    float* T  = sm;               // epilogue reuse: [128 m][68 d]

    int t = threadIdx.x;
    int head = blockIdx.y;
    int r0 = blockIdx.x * 128;
    int b = r0 >> 10, nb = r0 & 1023;
    int bh = b * HEADS_ + head;

    #pragma unroll
    for (int i = 0; i < 16; i++) {
        int f = t + i * 256;
        int row = f >> 5, c4 = f & 31;
        uint4 v = *(const uint4*)(h + (size_t)(r0 + row) * IND_ + c4 * 4);
        v.x += 0x1000u; v.y += 0x1000u; v.z += 0x1000u; v.w += 0x1000u;
        *(uint4*)(hA + row * 136 + c4 * 4) = v;
    }
    #pragma unroll
    for (int i = 0; i < 8; i++) {
        int f = t + i * 256;
        int k = f >> 4, d4 = f & 15;
        uint4 v = *(const uint4*)(W + (size_t)head * (IND_ * HD_) + k * HD_ + d4 * 4);
        v.x += 0x1000u; v.y += 0x1000u; v.z += 0x1000u; v.w += 0x1000u;
        *(uint4*)(WB + k * 68 + d4 * 4) = v;
    }
    __syncthreads();

    int w = t >> 5, lane = t & 31, qr = lane >> 2, qm = lane & 3;
    int rA = w * 16 + qr;

    float c[8][4];
    #pragma unroll
    for (int j = 0; j < 8; j++)
        #pragma unroll
        for (int q = 0; q < 4; q++) c[j][q] = 0.f;

    #pragma unroll
    for (int ks = 0; ks < 16; ks++) {
        int k0 = ks * 8;
        uint32_t a0 = __float_as_uint(hA[rA * 136 + k0 + qm]);
        uint32_t a1 = __float_as_uint(hA[(rA + 8) * 136 + k0 + qm]);
        uint32_t a2 = __float_as_uint(hA[rA * 136 + k0 + qm + 4]);
        uint32_t a3 = __float_as_uint(hA[(rA + 8) * 136 + k0 + qm + 4]);
        const float* b0r = WB + (k0 + qm) * 68 + qr;
        const float* b1r = WB + (k0 + qm + 4) * 68 + qr;
        #pragma unroll
        for (int j = 0; j < 8; j++) {
            mma_tf32(c[j], a0, a1, a2, a3,
                     __float_as_uint(b0r[8 * j]), __float_as_uint(b1r[8 * j]));
        }
    }

    {
        const float* ah = a + head * (2 * HD_);
        float ps0 = 0.f, ps1 = 0.f, pd0 = 0.f, pd1 = 0.f;
        #pragma unroll
        for (int j = 0; j < 8; j++) {
            float2 as = *(const float2*)(ah + 8 * j + 2 * qm);
            float2 ad = *(const float2*)(ah + HD_ + 8 * j + 2 * qm);
            ps0 += c[j][0] * as.x + c[j][1] * as.y;
            ps1 += c[j][2] * as.x + c[j][3] * as.y;
            pd0 += c[j][0] * ad.x + c[j][1] * ad.y;
            pd1 += c[j][2] * ad.x + c[j][3] * ad.y;
        }
        #pragma unroll
        for (int o = 1; o <= 2; o <<= 1) {
            ps0 += __shfl_xor_sync(0xFFFFFFFFu, ps0, o);
            ps1 += __shfl_xor_sync(0xFFFFFFFFu, ps1, o);
            pd0 += __shfl_xor_sync(0xFFFFFFFFu, pd0, o);
            pd1 += __shfl_xor_sync(0xFFFFFFFFu, pd1, o);
        }
        if (qm == 0) {
            int n = nb + rA;
            g_esrc[(size_t)bh * N_ + n] = ps0;
            g_edst[(size_t)bh * N_ + n] = pd0;
            g_esrc[(size_t)bh * N_ + n + 8] = ps1;
            g_edst[(size_t)bh * N_ + n + 8] = pd1;
        }
    }

    __syncthreads();
    #pragma unroll
    for (int j = 0; j < 8; j++) {
        *(float2*)(T + rA * 68 + 8 * j + 2 * qm)       = make_float2(c[j][0], c[j][1]);
        *(float2*)(T + (rA + 8) * 68 + 8 * j + 2 * qm) = make_float2(c[j][2], c[j][3]);
    }
    __syncthreads();

    {
        int s = nb >> 9;
        int mt0 = (nb & 511) >> 5;
        uint2* gbase = (uint2*)g_hpT16 + ((size_t)(bh * 2 + s)) * 8192 + mt0 * 512;
        #pragma unroll
        for (int i = 0; i < 8; i++) {
            int cidx = t + i * 256;
            int mtl = cidx >> 9, ks = (cidx >> 8) & 1, j = (cidx >> 5) & 7;
            int ln = cidx & 31, lqr = ln >> 2, lqm = ln & 3;
            int d = 8 * j + lqr;
            int m0 = mtl * 32 + ks * 16 + 2 * lqm;
            uint2 u;
            u.x = h2pack(T[m0 * 68 + d], T[(m0 + 1) * 68 + d]);
            u.y = h2pack(T[(m0 + 8) * 68 + d], T[(m0 + 9) * 68 + d]);
            gbase[mtl * 512 + ks * 256 + j * 32 + ln] = u;
        }
    }
}

// ============================================================================
// Kernel C: fp16 mma attention. CTA = 64 n rows, 256 thr = 8 warps (4 row-
// groups x 2 m-splits of 512 m). V staged in 2-mt chunks, 3 stages (8
// barriers/CTA, cp.async depth 2). Ones-column MMA denominator. grid (16,32),
// 4 CTAs/SM single wave.
// ============================================================================
#define SB_V     0                    // 3 stages x 16KB = 49152
#define SB_EDP   49152                // e_dst * log2e, permuted: 4096 B
#define SB_ESRC  53248                // 256 B
#define SB_RED   53504                // 64 B
#define SMEM_C   53568
#define CB_STRIDE 38

__global__ void __launch_bounds__(256, 4) attn_kernel(const float* __restrict__ h_in,
                                                      float* __restrict__ out) {
    extern __shared__ char smc[];
    const uint32_t sb = smem_u32(smc);
    float* edp    = (float*)(smc + SB_EDP);
    float* esrc_s = (float*)(smc + SB_ESRC);
    float* red    = (float*)(smc + SB_RED);
    float* cbuf   = (float*)(smc + SB_V);   // epilogue reuse

    int t = threadIdx.x, w = t >> 5, lane = t & 31;
    int qr = lane >> 2, qm = lane & 3;
    int ws = w >> 2, rg = w & 3;
    int bh = blockIdx.y, b = bh >> 1, head = bh & 1;
    int n0 = blockIdx.x * 64;

    // cp.async staging map: thread covers split ss, 32B per mt
    int ss = t >> 7, i128 = t & 127;
    const char* gsrc = (const char*)((const uint2*)g_hpT16 +
                       ((size_t)(bh * 2 + ss)) * 8192 + i128 * 4);
    uint32_t sdst = sb + SB_V + ss * 4096 + i128 * 32;

    // prologue: stage pairs 0 and 1 (mt 0-3), one commit each
    #pragma unroll
    for (int pp = 0; pp < 2; pp++) {
        #pragma unroll
        for (int m = 0; m < 2; m++) {
            const char* gs = gsrc + (size_t)(2 * pp + m) * 4096;
            uint32_t sd = sdst + pp * 16384 + m * 8192;
            cp16(sd, gs);
            cp16(sd + 16, gs + 16);
        }
        CP_COMMIT();
    }

    // e_dst -> edp (scaled by log2e, fragment-permuted) + block max
    float4 ed4 = *(const float4*)(g_edst + (size_t)bh * N_ + t * 4);
    ed4.x *= LOG2E_; ed4.y *= LOG2E_; ed4.z *= LOG2E_; ed4.w *= LOG2E_;
    {
        float lm = fmaxf(fmaxf(ed4.x, ed4.y), fmaxf(ed4.z, ed4.w));
        #pragma unroll
        for (int o = 16; o; o >>= 1) lm = fmaxf(lm, __shfl_xor_sync(0xFFFFFFFFu, lm, o));
        if (lane == 0) red[w] = lm;
        float edv[4] = {ed4.x, ed4.y, ed4.z, ed4.w};
        #pragma unroll
        for (int e = 0; e < 4; e++) {
            int m = 4 * t + e;
            int g = m >> 4, q = m & 15;
            int dsti = (q < 8) ? ((q >> 1) * 4 + (q & 1))
                               : ((q - 8) >> 1) * 4 + 2 + (q & 1);
            edp[g * 16 + dsti] = edv[e];
        }
    }
    if (t < 64) esrc_s[t] = g_esrc[(size_t)bh * N_ + n0 + t] * LOG2E_;
    __syncthreads();
    if (t == 0) {
        float m = red[0];
        #pragma unroll
        for (int i = 1; i < 8; i++) m = fmaxf(m, red[i]);
        red[0] = m;
    }
    __syncthreads();
    float MxL = red[0];

    // per-thread row constants (log2 domain)
    int r = rg * 16 + qr;
    float esL0 = esrc_s[r], esL1 = esrc_s[r + 8];
    float x0 = esL0 + MxL, x1 = esL1 + MxL;
    float cb0 = -fmaxf(x0, ALPHA_ * x0);
    float cb1 = -fmaxf(x1, ALPHA_ * x1);
    float p0 = esL0 + cb0, q0 = fmaf(ALPHA_, esL0, cb0);
    float p1 = esL1 + cb1, q1 = fmaf(ALPHA_, esL1, cb1);

    float c[9][4];
    #pragma unroll
    for (int j = 0; j < 9; j++)
        #pragma unroll
        for (int q = 0; q < 4; q++) c[j][q] = 0.f;

    const uint32_t ONE2 = 0x3C003C00u;
    const float* edw = edp + (ws * 32) * 16 + 4 * qm;   // this warp's e-slice

    for (int p = 0; p < 8; p++) {
        if (p < 7) { CP_WAIT(1); } else { CP_WAIT(0); }
        __syncthreads();   // fresh stage visible AND stage (p+2)%3 fully consumed
        if (p < 6) {
            int pn = p + 2;
            uint32_t sd = sdst + (uint32_t)(pn % 3) * 16384;
            const char* gs = gsrc + (size_t)(2 * pn) * 4096;
            cp16(sd, gs);
            cp16(sd + 16, gs + 16);
            cp16(sd + 8192, gs + 4096);
            cp16(sd + 8192 + 16, gs + 4096 + 16);
            CP_COMMIT();
        }
        const char* stb = smc + SB_V + (p % 3) * 16384 + ws * 4096;
        #pragma unroll
        for (int msub = 0; msub < 2; msub++) {
            int mt = 2 * p + msub;
            const uint2* Vb2 = (const uint2*)(stb + msub * 8192) + lane;
            #pragma unroll
            for (int ks = 0; ks < 2; ks++) {
                float4 e4 = *(const float4*)(edw + (mt * 2 + ks) * 16);
                uint32_t a0 = h2pack(wexp4(e4.x, p0, q0), wexp4(e4.y, p0, q0));
                uint32_t a1 = h2pack(wexp4(e4.x, p1, q1), wexp4(e4.y, p1, q1));
                uint32_t a2 = h2pack(wexp4(e4.z, p0, q0), wexp4(e4.w, p0, q0));
                uint32_t a3 = h2pack(wexp4(e4.z, p1, q1), wexp4(e4.w, p1, q1));
                const uint2* bp = Vb2 + ks * 256;
                #pragma unroll
                for (int j = 0; j < 8; j++) {
                    uint2 bb = bp[j * 32];
                    mma_f16(c[j], a0, a1, a2, a3, bb.x, bb.y);
                }
                mma_f16(c[8], a0, a1, a2, a3, ONE2, ONE2);
            }
        }
    }
    __syncthreads();   // all V reads done before cbuf overlays SB_V

    // combine m-splits: warps 4-7 export, warps 0-3 add + epilogue
    if (ws == 1) {
        float* cb = cbuf + (rg * 32 + lane) * CB_STRIDE;
        #pragma unroll
        for (int j = 0; j < 9; j++) {
            *(float2*)(cb + 4 * j)     = make_float2(c[j][0], c[j][1]);
            *(float2*)(cb + 4 * j + 2) = make_float2(c[j][2], c[j][3]);
        }
    }
    __syncthreads();
    if (ws == 0) {
        const float* cb = cbuf + (rg * 32 + lane) * CB_STRIDE;
        #pragma unroll
        for (int j = 0; j < 9; j++) {
            float2 pa = *(const float2*)(cb + 4 * j);
            float2 pb = *(const float2*)(cb + 4 * j + 2);
            c[j][0] += pa.x; c[j][1] += pa.y; c[j][2] += pb.x; c[j][3] += pb.y;
        }
        float inv0 = 1.0f / c[8][0];
        float inv1 = 1.0f / c[8][2];
        int n_row = n0 + r;
        #pragma unroll
        for (int j = 0; j < 8; j++) {
            int d0 = 8 * j + 2 * qm;
            size_t base0 = ((size_t)(b * N_ + n_row)) * IND_ + head * HD_ + d0;
            float2 hv0 = *(const float2*)(h_in + base0);
            float ox = c[j][0] * inv0 + hv0.x;
            float oy = c[j][1] * inv0 + hv0.y;
            ox = ox > 0.f ? ox : expm1f(ox);
            oy = oy > 0.f ? oy : expm1f(oy);
            *(float2*)(out + base0) = make_float2(ox, oy);

            size_t base1 = base0 + (size_t)8 * IND_;
            float2 hv1 = *(const float2*)(h_in + base1);
            float oz = c[j][2] * inv1 + hv1.x;
            float ow = c[j][3] * inv1 + hv1.y;
            oz = oz > 0.f ? oz : expm1f(oz);
            ow = ow > 0.f ? ow : expm1f(ow);
            *(float2*)(out + base1) = make_float2(oz, ow);
        }
    }
}

// ============================================================================
extern "C" void kernel_launch(void* const* d_in, const int* in_sizes, int n_in,
                              void* d_out, int out_size) {
    const float* h = (const float*)d_in[0];
    const float* W = (const float*)d_in[1];
    const float* a = (const float*)d_in[2];
    float* out = (float*)d_out;

    const int smemA = (128 * 136 + 128 * 68) * 4;   // 104448 B
    cudaFuncSetAttribute(proj_kernel, cudaFuncAttributeMaxDynamicSharedMemorySize, smemA);
    cudaFuncSetAttribute(attn_kernel, cudaFuncAttributeMaxDynamicSharedMemorySize, SMEM_C);

    proj_kernel<<<dim3(128, 2), 256, smemA>>>(h, W, a);
    attn_kernel<<<dim3(16, 32), 256, SMEM_C>>>(h, out);
    (void)in_sizes; (void)n_in; (void)out_size;
}